// round 3
// baseline (speedup 1.0000x reference)
#include <cuda_runtime.h>
#include <cuda_bf16.h>

// Problem constants
#define JJ   19
#define PP   100000
#define RR   16
#define NIN  32
#define NOUT 36
#define FPA  12               // features per axis
#define OO   (NOUT * RR)      // 576 = per-j output width of ParallelLinear
#define AJ   (3 * RR * NOUT)  // 1728 floats of folded matrix per j

#define TP   256              // points per block (== threads per block)
#define PAD  38               // padded row stride (even -> float2-aligned, conflict-free)

// Folded per-volume matrix: A[j][c][r][co], unpadded in global scratch.
__device__ float g_A[JJ * AJ];

// ---------------------------------------------------------------------------
// Kernel 1: tiny precompute.
//   feat[j,f,r,c] = sum_i latent[j,i] * pl_w[j,i,(f*R+r)*3+c] + pl_b[j,(f*R+r)*3+c]
//   A[j,c,r,co]   = sum_f map_w[co, f*3+c] * feat[j,f,r,c]
// One block per j, 576 threads.
// ---------------------------------------------------------------------------
__global__ __launch_bounds__(OO) void vf_prep_kernel(
    const float* __restrict__ latent,   // [1, J, 32]
    const float* __restrict__ pl_w,     // [J, 32, 576]
    const float* __restrict__ pl_b,     // [J, 576]
    const float* __restrict__ map_w)    // [36, 36]
{
    const int j = blockIdx.x;
    const int t = threadIdx.x;

    __shared__ float lat_s[NIN];
    __shared__ float feat_s[OO];

    if (t < NIN) lat_s[t] = latent[j * NIN + t];
    __syncthreads();

    // ParallelLinear for this j (coalesced over o)
    {
        const float* wp = pl_w + (size_t)j * NIN * OO + t;
        float s = pl_b[(size_t)j * OO + t];
        #pragma unroll
        for (int i = 0; i < NIN; i++)
            s = fmaf(lat_s[i], wp[i * OO], s);
        feat_s[t] = s;
    }
    __syncthreads();

    // Fold mapper into features: 1728 entries, 3 per thread
    for (int e = t; e < AJ; e += OO) {
        const int co = e % NOUT;
        const int rr = (e / NOUT) % RR;
        const int c  = e / (NOUT * RR);
        float s = 0.f;
        #pragma unroll
        for (int f = 0; f < FPA; f++)
            s = fmaf(map_w[co * NOUT + f * 3 + c], feat_s[(f * RR + rr) * 3 + c], s);
        g_A[(size_t)j * AJ + e] = s;
    }
}

// ---------------------------------------------------------------------------
// Kernel 2: main sampling kernel.
// grid = (ceil(P/TP), J). Each block: one j, TP points, one thread per point.
//   per point: 3x (i0, w) -> 36-channel accumulation from 6 padded A rows
//   (float2 LDS) -> stage in padded smem -> fully coalesced float2 store.
// ---------------------------------------------------------------------------
__global__ __launch_bounds__(TP) void vf_main_kernel(
    const float* __restrict__ pts,     // [J, P, 3]
    const float* __restrict__ map_b,   // [36]
    float* __restrict__ out)           // [J, P, 36]
{
    const int j  = blockIdx.y;
    const int p0 = blockIdx.x * TP;
    const int t  = threadIdx.x;

    __shared__ float As[3 * RR * PAD];   // padded rows: row = c*16+r, stride 38
    __shared__ float bias_s[NOUT];
    __shared__ float st[TP * PAD];       // output staging, padded

    // Load this volume's folded matrix into padded smem (coalesced from global)
    for (int e = t; e < AJ; e += TP) {
        const int co  = e % NOUT;
        const int row = e / NOUT;        // c*16 + r
        As[row * PAD + co] = g_A[(size_t)j * AJ + e];
    }
    if (t < NOUT) bias_s[t] = map_b[t];
    __syncthreads();

    const int p = p0 + t;
    const bool valid = (p < PP);

    if (valid) {
        const float* pp = pts + ((size_t)j * PP + p) * 3;
        float px = pp[0], py = pp[1], pz = pp[2];

        float w[3], wm[3];
        int base[3];
        #pragma unroll
        for (int c = 0; c < 3; c++) {
            float v = (c == 0) ? px : (c == 1) ? py : pz;
            float u = (v + 1.0f) * 7.5f;                 // 0.5 * (R-1)
            u = fminf(fmaxf(u, 0.0f), 15.0f);
            int i0 = (int)u;                             // floor (u >= 0)
            i0 = min(i0, RR - 2);
            w[c]  = u - (float)i0;
            wm[c] = 1.0f - w[c];
            base[c] = (c * RR + i0) * PAD;
        }

        float acc[NOUT];
        #pragma unroll
        for (int k = 0; k < NOUT; k++) acc[k] = bias_s[k];

        #pragma unroll
        for (int c = 0; c < 3; c++) {
            const float2* r0 = (const float2*)(As + base[c]);
            const float2* r1 = (const float2*)(As + base[c] + PAD);
            const float wmc = wm[c];
            const float wc  = w[c];
            #pragma unroll
            for (int k = 0; k < NOUT / 2; k++) {
                float2 a0 = r0[k];
                float2 a1 = r1[k];
                acc[2*k]   = fmaf(wmc, a0.x, acc[2*k]);
                acc[2*k]   = fmaf(wc,  a1.x, acc[2*k]);
                acc[2*k+1] = fmaf(wmc, a0.y, acc[2*k+1]);
                acc[2*k+1] = fmaf(wc,  a1.y, acc[2*k+1]);
            }
        }

        // stage (even padded stride -> aligned float2 STS, conflict-free)
        float2* str = (float2*)(st + t * PAD);
        #pragma unroll
        for (int k = 0; k < NOUT / 2; k++)
            str[k] = make_float2(acc[2*k], acc[2*k+1]);
    }
    __syncthreads();

    // Coalesced float2 copy-out of the tile (divide-free q/co walk)
    const int nvalid = min(TP, PP - p0);
    const int total2 = (nvalid * NOUT) / 2;        // NOUT even -> exact
    float2* outp = (float2*)(out + ((size_t)j * PP + p0) * NOUT);
    {
        int e  = t * 2;                  // element index of first pair
        int q  = e / NOUT;               // one divide at setup
        int co = e - q * NOUT;
        for (int idx = t; idx < total2; idx += TP) {
            outp[idx] = *(const float2*)(st + q * PAD + co);
            // advance by TP pairs = 2*TP elements = 512 = 14*36 + 8
            q  += (2 * TP) / NOUT;                 // +14
            co += (2 * TP) % NOUT;                 // +8
            if (co >= NOUT) { co -= NOUT; q += 1; }
        }
    }
}

// ---------------------------------------------------------------------------
// Launch
// inputs (metadata order): pts, latent, pl_w, pl_b, map_w, map_b
// ---------------------------------------------------------------------------
extern "C" void kernel_launch(void* const* d_in, const int* in_sizes, int n_in,
                              void* d_out, int out_size)
{
    const float* pts    = (const float*)d_in[0];
    const float* latent = (const float*)d_in[1];
    const float* pl_w   = (const float*)d_in[2];
    const float* pl_b   = (const float*)d_in[3];
    const float* map_w  = (const float*)d_in[4];
    const float* map_b  = (const float*)d_in[5];
    float* out = (float*)d_out;

    vf_prep_kernel<<<JJ, OO>>>(latent, pl_w, pl_b, map_w);

    dim3 grid((PP + TP - 1) / TP, JJ);
    vf_main_kernel<<<grid, TP>>>(pts, map_b, out);
}

// round 6
// speedup vs baseline: 1.1388x; 1.1388x over previous
#include <cuda_runtime.h>
#include <cuda_fp16.h>
#include <cuda_bf16.h>

// Problem constants
#define JJ   19
#define PP   100000
#define RR   16
#define NIN  32
#define NOUT 36
#define FPA  12               // features per axis
#define OO   (NOUT * RR)      // 576 = per-j output width of ParallelLinear
#define AJ   (3 * RR * NOUT)  // 1728 entries of folded matrix per j

#define TP   256              // points per block (== threads per block)
#define PADS 38               // staging row stride (floats, even -> float2, conflict-free)

// Folded per-volume matrix in fp16: A[j][c*16+r][co], row stride 36 halves (72 B).
// 72B row stride is conflict-free for arbitrary row mixes (72*d mod 128 != 0, d=1..15).
__device__ __align__(16) __half g_Ah[JJ * AJ];

// ---------------------------------------------------------------------------
// Kernel 1: tiny precompute (fp32 math, fp16 store).
//   feat[j,f,r,c] = sum_i latent[j,i] * pl_w[j,i,(f*R+r)*3+c] + pl_b[j,(f*R+r)*3+c]
//   A[j,c,r,co]   = sum_f map_w[co, f*3+c] * feat[j,f,r,c]
// One block per j, 576 threads.
// ---------------------------------------------------------------------------
__global__ __launch_bounds__(OO) void vf_prep_kernel(
    const float* __restrict__ latent,   // [1, J, 32]
    const float* __restrict__ pl_w,     // [J, 32, 576]
    const float* __restrict__ pl_b,     // [J, 576]
    const float* __restrict__ map_w)    // [36, 36]
{
    const int j = blockIdx.x;
    const int t = threadIdx.x;

    __shared__ float lat_s[NIN];
    __shared__ float feat_s[OO];

    if (t < NIN) lat_s[t] = latent[j * NIN + t];
    __syncthreads();

    // ParallelLinear for this j (coalesced over o)
    {
        const float* wp = pl_w + (size_t)j * NIN * OO + t;
        float s = pl_b[(size_t)j * OO + t];
        #pragma unroll
        for (int i = 0; i < NIN; i++)
            s = fmaf(lat_s[i], wp[i * OO], s);
        feat_s[t] = s;
    }
    __syncthreads();

    // Fold mapper into features: 1728 entries, 3 per thread
    for (int e = t; e < AJ; e += OO) {
        const int co = e % NOUT;
        const int rr = (e / NOUT) % RR;
        const int c  = e / (NOUT * RR);
        float s = 0.f;
        #pragma unroll
        for (int f = 0; f < FPA; f++)
            s = fmaf(map_w[co * NOUT + f * 3 + c], feat_s[(f * RR + rr) * 3 + c], s);
        g_Ah[(size_t)j * AJ + e] = __float2half_rn(s);
    }
}

// ---------------------------------------------------------------------------
// Kernel 2: main sampling kernel.
// grid = (ceil(P/TP), J). One thread per point.
//   fp16 A rows in smem (72B stride, conflict-free) -> fp32 accumulation
//   -> padded fp32 staging -> fully coalesced float2 global store.
// ---------------------------------------------------------------------------
__global__ __launch_bounds__(TP) void vf_main_kernel(
    const float* __restrict__ pts,     // [J, P, 3]
    const float* __restrict__ map_b,   // [36]
    float* __restrict__ out)           // [J, P, 36]
{
    const int j  = blockIdx.y;
    const int p0 = blockIdx.x * TP;
    const int t  = threadIdx.x;

    __shared__ __align__(16) __half As_h[AJ];     // 3456 B, rows of 36 halves
    __shared__ float bias_s[NOUT];
    __shared__ __align__(16) float st[TP * PADS]; // output staging, padded

    // Copy this volume's folded fp16 matrix (same layout, raw uint4 copy)
    {
        const uint4* src = (const uint4*)(g_Ah + (size_t)j * AJ);  // AJ*2 = 3456 B = 216 uint4
        uint4* dst = (uint4*)As_h;
        for (int e = t; e < (AJ * 2) / 16; e += TP)
            dst[e] = src[e];
    }
    if (t < NOUT) bias_s[t] = map_b[t];
    __syncthreads();

    const int p = p0 + t;
    const bool valid = (p < PP);

    if (valid) {
        const float* pp = pts + ((size_t)j * PP + p) * 3;
        float px = pp[0], py = pp[1], pz = pp[2];

        float w[3], wm[3];
        int base[3];                              // byte offset of row (c*16+i0)
        #pragma unroll
        for (int c = 0; c < 3; c++) {
            float v = (c == 0) ? px : (c == 1) ? py : pz;
            float u = (v + 1.0f) * 7.5f;          // 0.5 * (R-1)
            u = fminf(fmaxf(u, 0.0f), 15.0f);
            int i0 = (int)u;                      // floor (u >= 0)
            i0 = min(i0, RR - 2);
            w[c]  = u - (float)i0;
            wm[c] = 1.0f - w[c];
            base[c] = (c * RR + i0) * (NOUT * 2); // 72 B per row
        }

        float acc[NOUT];
        #pragma unroll
        for (int k = 0; k < NOUT; k++) acc[k] = bias_s[k];

        #pragma unroll
        for (int c = 0; c < 3; c++) {
            const char* r0b = (const char*)As_h + base[c];
            const float wmc = wm[c];
            const float wc  = w[c];
            #pragma unroll
            for (int k = 0; k < 9; k++) {         // 9 x uint2 = 36 halves per row
                uint2 u0 = ((const uint2*)r0b)[k];
                uint2 u1 = ((const uint2*)(r0b + NOUT * 2))[k];
                float2 a0 = __half22float2(*(const __half2*)&u0.x);
                float2 b0 = __half22float2(*(const __half2*)&u0.y);
                float2 a1 = __half22float2(*(const __half2*)&u1.x);
                float2 b1 = __half22float2(*(const __half2*)&u1.y);
                acc[4*k+0] = fmaf(wmc, a0.x, fmaf(wc, a1.x, acc[4*k+0]));
                acc[4*k+1] = fmaf(wmc, a0.y, fmaf(wc, a1.y, acc[4*k+1]));
                acc[4*k+2] = fmaf(wmc, b0.x, fmaf(wc, b1.x, acc[4*k+2]));
                acc[4*k+3] = fmaf(wmc, b0.y, fmaf(wc, b1.y, acc[4*k+3]));
            }
        }

        // stage (even padded stride -> aligned float2 STS, conflict-free)
        float2* str = (float2*)(st + t * PADS);
        #pragma unroll
        for (int k = 0; k < NOUT / 2; k++)
            str[k] = make_float2(acc[2*k], acc[2*k+1]);
    }
    __syncthreads();

    // Coalesced float2 copy-out of the tile (divide-free q/co walk)
    const int nvalid = min(TP, PP - p0);
    const int total2 = (nvalid * NOUT) / 2;        // NOUT even -> exact
    float2* outp = (float2*)(out + ((size_t)j * PP + p0) * NOUT);
    {
        int e  = t * 2;                  // element index of first pair
        int q  = e / NOUT;               // one divide at setup
        int co = e - q * NOUT;
        for (int idx = t; idx < total2; idx += TP) {
            outp[idx] = *(const float2*)(st + q * PADS + co);
            // advance by TP pairs = 2*TP elements = 512 = 14*36 + 8
            q  += (2 * TP) / NOUT;                 // +14
            co += (2 * TP) % NOUT;                 // +8
            if (co >= NOUT) { co -= NOUT; q += 1; }
        }
    }
}

// ---------------------------------------------------------------------------
// Launch
// inputs (metadata order): pts, latent, pl_w, pl_b, map_w, map_b
// ---------------------------------------------------------------------------
extern "C" void kernel_launch(void* const* d_in, const int* in_sizes, int n_in,
                              void* d_out, int out_size)
{
    const float* pts    = (const float*)d_in[0];
    const float* latent = (const float*)d_in[1];
    const float* pl_w   = (const float*)d_in[2];
    const float* pl_b   = (const float*)d_in[3];
    const float* map_w  = (const float*)d_in[4];
    const float* map_b  = (const float*)d_in[5];
    float* out = (float*)d_out;

    vf_prep_kernel<<<JJ, OO>>>(latent, pl_w, pl_b, map_w);

    dim3 grid((PP + TP - 1) / TP, JJ);
    vf_main_kernel<<<grid, TP>>>(pts, map_b, out);
}

// round 8
// speedup vs baseline: 1.4522x; 1.2751x over previous
#include <cuda_runtime.h>
#include <cuda_fp16.h>
#include <cuda_bf16.h>

// Problem constants
#define JJ   19
#define PP   100000
#define RR   16
#define NIN  32
#define NOUT 36
#define FPA  12               // features per axis
#define OO   (NOUT * RR)      // 576 = per-j output width of ParallelLinear
#define AJ   (3 * RR * NOUT)  // 1728 entries of folded matrix per j

#define TP   256              // points per block (== threads per block)
#define PADS 38               // staging row stride (floats, even -> float2, conflict-free)
#define NCH  12               // channels per chunk (3 chunks of 12)

// Folded per-volume matrix in fp16: A[j][c*16+r][co], row stride 36 halves (72 B).
// 72B row stride is conflict-free for arbitrary row mixes (72*d mod 128 != 0, d=1..15).
__device__ __align__(16) __half g_Ah[JJ * AJ];

// ---------------------------------------------------------------------------
// Kernel 1: tiny precompute (fp32 math, fp16 store).
// ---------------------------------------------------------------------------
__global__ __launch_bounds__(OO) void vf_prep_kernel(
    const float* __restrict__ latent,   // [1, J, 32]
    const float* __restrict__ pl_w,     // [J, 32, 576]
    const float* __restrict__ pl_b,     // [J, 576]
    const float* __restrict__ map_w)    // [36, 36]
{
    const int j = blockIdx.x;
    const int t = threadIdx.x;

    __shared__ float lat_s[NIN];
    __shared__ float feat_s[OO];

    if (t < NIN) lat_s[t] = latent[j * NIN + t];
    __syncthreads();

    {
        const float* wp = pl_w + (size_t)j * NIN * OO + t;
        float s = pl_b[(size_t)j * OO + t];
        #pragma unroll
        for (int i = 0; i < NIN; i++)
            s = fmaf(lat_s[i], wp[i * OO], s);
        feat_s[t] = s;
    }
    __syncthreads();

    for (int e = t; e < AJ; e += OO) {
        const int co = e % NOUT;
        const int rr = (e / NOUT) % RR;
        const int c  = e / (NOUT * RR);
        float s = 0.f;
        #pragma unroll
        for (int f = 0; f < FPA; f++)
            s = fmaf(map_w[co * NOUT + f * 3 + c], feat_s[(f * RR + rr) * 3 + c], s);
        g_Ah[(size_t)j * AJ + e] = __float2half_rn(s);
    }
}

// ---------------------------------------------------------------------------
// Kernel 2: main sampling kernel.
// grid = (ceil(P/TP), J). One thread per point.
// Channels processed in 3 chunks of 12 (non-unrolled chunk loop) to cap the
// accumulator live range -> low register count -> high occupancy.
// ---------------------------------------------------------------------------
__global__ __launch_bounds__(TP) void vf_main_kernel(
    const float* __restrict__ pts,     // [J, P, 3]
    const float* __restrict__ map_b,   // [36]
    float* __restrict__ out)           // [J, P, 36]
{
    const int j  = blockIdx.y;
    const int p0 = blockIdx.x * TP;
    const int t  = threadIdx.x;

    __shared__ __align__(16) __half As_h[AJ];     // 3456 B, rows of 36 halves
    __shared__ float bias_s[NOUT];
    __shared__ __align__(16) float st[TP * PADS]; // output staging, padded

    // Copy this volume's folded fp16 matrix (uint4 copy)
    {
        const uint4* src = (const uint4*)(g_Ah + (size_t)j * AJ);  // 216 uint4
        uint4* dst = (uint4*)As_h;
        for (int e = t; e < (AJ * 2) / 16; e += TP)
            dst[e] = src[e];
    }
    if (t < NOUT) bias_s[t] = map_b[t];
    __syncthreads();

    const int p = p0 + t;
    const bool valid = (p < PP);

    if (valid) {
        const float* pp = pts + ((size_t)j * PP + p) * 3;
        float px = pp[0], py = pp[1], pz = pp[2];

        float w[3], wm[3];
        int base[3];                              // byte offset of row (c*16+i0)
        #pragma unroll
        for (int c = 0; c < 3; c++) {
            float v = (c == 0) ? px : (c == 1) ? py : pz;
            float u = (v + 1.0f) * 7.5f;          // 0.5 * (R-1)
            u = fminf(fmaxf(u, 0.0f), 15.0f);
            int i0 = (int)u;                      // floor (u >= 0)
            i0 = min(i0, RR - 2);
            w[c]  = u - (float)i0;
            wm[c] = 1.0f - w[c];
            base[c] = (c * RR + i0) * (NOUT * 2); // 72 B per row
        }

        // 3 chunks of 12 channels; loop NOT unrolled (keeps regs low)
        #pragma unroll 1
        for (int ch = 0; ch < 3; ch++) {
            const int cb = ch * NCH;              // channel base
            float acc[NCH];
            #pragma unroll
            for (int k = 0; k < NCH; k++) acc[k] = bias_s[cb + k];

            #pragma unroll
            for (int c = 0; c < 3; c++) {
                const char* rb = (const char*)As_h + base[c] + cb * 2;
                const float wmc = wm[c];
                const float wc  = w[c];
                #pragma unroll
                for (int k = 0; k < 3; k++) {     // 3 x uint2 = 12 halves
                    uint2 u0 = ((const uint2*)rb)[k];
                    uint2 u1 = ((const uint2*)(rb + NOUT * 2))[k];
                    float2 a0 = __half22float2(*(const __half2*)&u0.x);
                    float2 b0 = __half22float2(*(const __half2*)&u0.y);
                    float2 a1 = __half22float2(*(const __half2*)&u1.x);
                    float2 b1 = __half22float2(*(const __half2*)&u1.y);
                    acc[4*k+0] = fmaf(wmc, a0.x, fmaf(wc, a1.x, acc[4*k+0]));
                    acc[4*k+1] = fmaf(wmc, a0.y, fmaf(wc, a1.y, acc[4*k+1]));
                    acc[4*k+2] = fmaf(wmc, b0.x, fmaf(wc, b1.x, acc[4*k+2]));
                    acc[4*k+3] = fmaf(wmc, b0.y, fmaf(wc, b1.y, acc[4*k+3]));
                }
            }

            // stage this chunk (aligned float2 STS, conflict-free)
            float2* str = (float2*)(st + t * PADS + cb);
            #pragma unroll
            for (int k = 0; k < NCH / 2; k++)
                str[k] = make_float2(acc[2*k], acc[2*k+1]);
        }
    }
    __syncthreads();

    // Coalesced float2 copy-out of the tile (divide-free q/co walk)
    const int nvalid = min(TP, PP - p0);
    const int total2 = (nvalid * NOUT) / 2;        // NOUT even -> exact
    float2* outp = (float2*)(out + ((size_t)j * PP + p0) * NOUT);
    {
        int e  = t * 2;                  // element index of first pair
        int q  = e / NOUT;               // one divide at setup
        int co = e - q * NOUT;
        for (int idx = t; idx < total2; idx += TP) {
            outp[idx] = *(const float2*)(st + q * PADS + co);
            // advance by TP pairs = 2*TP elements = 512 = 14*36 + 8
            q  += (2 * TP) / NOUT;                 // +14
            co += (2 * TP) % NOUT;                 // +8
            if (co >= NOUT) { co -= NOUT; q += 1; }
        }
    }
}

// ---------------------------------------------------------------------------
// Launch
// inputs (metadata order): pts, latent, pl_w, pl_b, map_w, map_b
// ---------------------------------------------------------------------------
extern "C" void kernel_launch(void* const* d_in, const int* in_sizes, int n_in,
                              void* d_out, int out_size)
{
    const float* pts    = (const float*)d_in[0];
    const float* latent = (const float*)d_in[1];
    const float* pl_w   = (const float*)d_in[2];
    const float* pl_b   = (const float*)d_in[3];
    const float* map_w  = (const float*)d_in[4];
    const float* map_b  = (const float*)d_in[5];
    float* out = (float*)d_out;

    vf_prep_kernel<<<JJ, OO>>>(latent, pl_w, pl_b, map_w);

    dim3 grid((PP + TP - 1) / TP, JJ);
    vf_main_kernel<<<grid, TP>>>(pts, map_b, out);
}